// round 5
// baseline (speedup 1.0000x reference)
#include <cuda_runtime.h>
#include <cuda_bf16.h>

#define SEQ   4096
#define BATCH 256
#define DIN   64
#define DH    128

// 512 MB scratch for the precomputed input projections x_proj[s][b][j].
// __device__ global (allocation-free per harness rules).
__device__ float g_xproj[SEQ * BATCH * DH];

// ---------------------------------------------------------------------------
// Packed fp32x2 helpers (Blackwell-only: 2 FMAs per instruction, rt=2/SMSP,
// i.e. 2x the scalar FFMA throughput).
// ---------------------------------------------------------------------------
__device__ __forceinline__ unsigned long long pack2(float lo, float hi) {
    unsigned long long r;
    asm("mov.b64 %0, {%1, %2};" : "=l"(r) : "f"(lo), "f"(hi));
    return r;
}

__device__ __forceinline__ float2 unpack2(unsigned long long v) {
    float2 f;
    asm("mov.b64 {%0, %1}, %2;" : "=f"(f.x), "=f"(f.y) : "l"(v));
    return f;
}

__device__ __forceinline__ void ffma2(unsigned long long& d,
                                      unsigned long long a,
                                      unsigned long long b) {
    // d = a * b + d   (elementwise on two packed fp32 lanes)
    asm("fma.rn.f32x2 %0, %1, %2, %0;" : "+l"(d) : "l"(a), "l"(b));
}

// tanh via 2x MUFU (EX2 + RCP), rel err ~2^-20; saturates correctly at +-inf.
__device__ __forceinline__ float fast_tanh(float x) {
    float e = __expf(x + x);
    return 1.0f - __fdividef(2.0f, e + 1.0f);
}

// ---------------------------------------------------------------------------
// Phase 1: x_proj[s,b,j] = sum_k input[s,b,k] * W_ih[j,k] + b_ih[j] + b_hh[j]
// Thread j owns output unit j; W_ih row j lives in 64 regs (32 f32x2 pairs).
// Blocks grid-stride over 16-row tiles of the flattened (s,b) dimension.
// ---------------------------------------------------------------------------
__global__ void __launch_bounds__(128) xproj_kernel(
    const float* __restrict__ in,     // [SEQ*BATCH, DIN]
    const float* __restrict__ Wih,    // [DH, DIN]
    const float* __restrict__ bA,     // [DH]
    const float* __restrict__ bB)     // [DH]
{
    __shared__ __align__(16) float sin_t[16][DIN];   // 4 KB tile

    const int j = threadIdx.x;

    // Pack W_ih row j as 32 f32x2 pairs (consecutive-k packing).
    unsigned long long wp[32];
#pragma unroll
    for (int q = 0; q < 16; q++) {
        float4 v = *(const float4*)(Wih + j * DIN + q * 4);
        wp[2 * q]     = pack2(v.x, v.y);
        wp[2 * q + 1] = pack2(v.z, v.w);
    }
    const float bias = bA[j] + bB[j];

    const int ntiles = (SEQ * BATCH) / 16;
    for (int tile = blockIdx.x; tile < ntiles; tile += gridDim.x) {
        __syncthreads();   // protect sin_t reuse (WAR from previous tile)
        // Cooperative load: 16 rows x 64 floats = 256 float4, 2 per thread.
        const float4* src = (const float4*)(in + tile * (16 * DIN));
        ((float4*)&sin_t[0][0])[j]       = src[j];
        ((float4*)&sin_t[0][0])[128 + j] = src[128 + j];
        __syncthreads();

        for (int r = 0; r < 16; r++) {
            unsigned long long a = 0ULL, b = 0ULL;   // two acc chains for ILP
#pragma unroll
            for (int q = 0; q < 16; q++) {
                ulonglong2 hv = *(const ulonglong2*)&sin_t[r][q * 4];
                ffma2(a, wp[2 * q],     hv.x);
                ffma2(b, wp[2 * q + 1], hv.y);
            }
            float2 fa = unpack2(a), fb = unpack2(b);
            g_xproj[(tile * 16 + r) * DH + j] =
                (fa.x + fa.y) + (fb.x + fb.y) + bias;
        }
    }
}

// ---------------------------------------------------------------------------
// Phase 2: sequential scan. 128 blocks x 256 threads.
// Block b owns batch rows {2b, 2b+1}; thread = (row-select, output unit j).
// W_hh row j in 128 regs (64 f32x2 pairs). h double-buffered in shared,
// one __syncthreads per step. x_proj prefetched 2 steps ahead.
// ---------------------------------------------------------------------------
__global__ void __launch_bounds__(256, 1) rnn_scan_kernel(
    const float* __restrict__ Whh,    // [DH, DH]
    float* __restrict__ out)          // [BATCH, DH]
{
    const int tid  = threadIdx.x;
    const int j    = tid & 127;
    const int rsel = tid >> 7;                  // 0 or 1
    const int row  = blockIdx.x * 2 + rsel;

    __shared__ __align__(16) float hbuf[2][2][DH];   // [buf][rsel][j]

    // Pack W_hh row j as 64 f32x2 pairs (128 registers).
    unsigned long long wp[64];
#pragma unroll
    for (int q = 0; q < 32; q++) {
        float4 v = *(const float4*)(Whh + j * DH + q * 4);
        wp[2 * q]     = pack2(v.x, v.y);
        wp[2 * q + 1] = pack2(v.z, v.w);
    }

    hbuf[0][rsel][j] = 0.0f;                    // h0 = 0

    // Prefetch x for steps 0 and 1 (distance-2 pipeline).
    float xc = __ldg(&g_xproj[(0 * BATCH + row) * DH + j]);
    float xn = __ldg(&g_xproj[(1 * BATCH + row) * DH + j]);
    __syncthreads();

    int   cur = 0;
    float hn  = 0.0f;
    for (int s = 0; s < SEQ; s++) {
        // Issue the prefetch for step s+2 first; consumed ~1.5 steps later.
        const int sp = (s + 2 < SEQ) ? (s + 2) : (SEQ - 1);
        float xf = __ldg(&g_xproj[(sp * BATCH + row) * DH + j]);

        const float* h = hbuf[cur][rsel];
        unsigned long long a = 0ULL, b = 0ULL;   // two dependency chains
#pragma unroll
        for (int q = 0; q < 32; q++) {
            ulonglong2 p = *(const ulonglong2*)(h + q * 4);   // LDS.128 broadcast
            ffma2(a, wp[2 * q],     p.x);
            ffma2(b, wp[2 * q + 1], p.y);
        }
        float2 fa = unpack2(a), fb = unpack2(b);
        hn = fast_tanh(xc + ((fa.x + fa.y) + (fb.x + fb.y)));

        hbuf[cur ^ 1][rsel][j] = hn;            // publish into the other buffer
        xc = xn; xn = xf;
        cur ^= 1;
        __syncthreads();                        // single barrier per step
    }

    out[row * DH + j] = hn;
}

// ---------------------------------------------------------------------------
// Launch: map inputs by element count (biases are interchangeable since only
// their sum is used), then phase-1 GEMM followed by the persistent scan.
// ---------------------------------------------------------------------------
extern "C" void kernel_launch(void* const* d_in, const int* in_sizes, int n_in,
                              void* d_out, int out_size) {
    const float* input = nullptr;
    const float* Wih   = nullptr;
    const float* Whh   = nullptr;
    const float* bA    = nullptr;
    const float* bB    = nullptr;

    for (int i = 0; i < n_in; i++) {
        const int sz = in_sizes[i];
        const float* p = (const float*)d_in[i];
        if      (sz == SEQ * BATCH * DIN) input = p;
        else if (sz == DH * DIN)          Wih   = p;
        else if (sz == DH * DH)           Whh   = p;
        else if (sz == DH)                { if (!bA) bA = p; else bB = p; }
    }

    xproj_kernel<<<2048, 128>>>(input, Wih, bA, bB);
    rnn_scan_kernel<<<BATCH / 2, 256>>>(Whh, (float*)d_out);
}

// round 6
// speedup vs baseline: 1.0504x; 1.0504x over previous
#include <cuda_runtime.h>
#include <cuda_bf16.h>

#define SEQ   4096
#define BATCH 256
#define DIN   64
#define DH    128

// 512 MB scratch for precomputed input projections x_proj[s][b][j].
__device__ float g_xproj[SEQ * BATCH * DH];

// ---------------------------------------------------------------------------
// Packed fp32x2 helpers (Blackwell: 2 FMAs per instruction).
// ---------------------------------------------------------------------------
__device__ __forceinline__ unsigned long long pack2(float lo, float hi) {
    unsigned long long r;
    asm("mov.b64 %0, {%1, %2};" : "=l"(r) : "f"(lo), "f"(hi));
    return r;
}

__device__ __forceinline__ float2 unpack2(unsigned long long v) {
    float2 f;
    asm("mov.b64 {%0, %1}, %2;" : "=f"(f.x), "=f"(f.y) : "l"(v));
    return f;
}

__device__ __forceinline__ void ffma2(unsigned long long& d,
                                      unsigned long long a,
                                      unsigned long long b) {
    asm("fma.rn.f32x2 %0, %1, %2, %0;" : "+l"(d) : "l"(a), "l"(b));
}

__device__ __forceinline__ unsigned long long fadd2(unsigned long long a,
                                                    unsigned long long b) {
    unsigned long long d;
    asm("add.rn.f32x2 %0, %1, %2;" : "=l"(d) : "l"(a), "l"(b));
    return d;
}

// tanh via 2x MUFU (EX2 + RCP), rel err ~2^-20.
__device__ __forceinline__ float fast_tanh(float x) {
    float e = __expf(x + x);
    return 1.0f - __fdividef(2.0f, e + 1.0f);
}

// ---------------------------------------------------------------------------
// Phase 1: x_proj[s,b,j] = dot(input[s,b,:], W_ih[j,:]) + b_ih[j] + b_hh[j]
// ---------------------------------------------------------------------------
__global__ void __launch_bounds__(128) xproj_kernel(
    const float* __restrict__ in,     // [SEQ*BATCH, DIN]
    const float* __restrict__ Wih,    // [DH, DIN]
    const float* __restrict__ bA,
    const float* __restrict__ bB)
{
    __shared__ __align__(16) float sin_t[16][DIN];   // 4 KB tile

    const int j = threadIdx.x;

    unsigned long long wp[32];
#pragma unroll
    for (int q = 0; q < 16; q++) {
        float4 v = *(const float4*)(Wih + j * DIN + q * 4);
        wp[2 * q]     = pack2(v.x, v.y);
        wp[2 * q + 1] = pack2(v.z, v.w);
    }
    const float bias = bA[j] + bB[j];

    const int ntiles = (SEQ * BATCH) / 16;
    for (int tile = blockIdx.x; tile < ntiles; tile += gridDim.x) {
        __syncthreads();   // WAR on sin_t reuse
        const float4* src = (const float4*)(in + tile * (16 * DIN));
        ((float4*)&sin_t[0][0])[j]       = src[j];
        ((float4*)&sin_t[0][0])[128 + j] = src[128 + j];
        __syncthreads();

        for (int r = 0; r < 16; r++) {
            unsigned long long acc[4] = {0ULL, 0ULL, 0ULL, 0ULL};  // depth-8 chains
#pragma unroll
            for (int q = 0; q < 16; q++) {
                ulonglong2 hv = *(const ulonglong2*)&sin_t[r][q * 4];
                ffma2(acc[(q & 1) * 2],     wp[2 * q],     hv.x);
                ffma2(acc[(q & 1) * 2 + 1], wp[2 * q + 1], hv.y);
            }
            unsigned long long t = fadd2(fadd2(acc[0], acc[1]),
                                         fadd2(acc[2], acc[3]));
            float2 f = unpack2(t);
            __stcs(&g_xproj[(tile * 16 + r) * DH + j], f.x + f.y + bias);
        }
    }
}

// ---------------------------------------------------------------------------
// Phase 2: sequential scan. 128 blocks x 256 threads.
// Block b owns batch rows {2b, 2b+1}. The two rows run as INDEPENDENT
// pipelines synchronized by per-row named barriers (bar.sync 1/2, 128),
// so their latency phases desynchronize and fill each other's issue slots.
// 8 accumulator chains (depth 8) + packed f32x2 reduction tree.
// ---------------------------------------------------------------------------
__global__ void __launch_bounds__(256, 1) rnn_scan_kernel(
    const float* __restrict__ Whh,    // [DH, DH]
    float* __restrict__ out)          // [BATCH, DH]
{
    const int tid  = threadIdx.x;
    const int j    = tid & 127;
    const int rsel = tid >> 7;                  // 0 or 1 (warp-uniform)
    const int row  = blockIdx.x * 2 + rsel;
    const int bar  = 1 + rsel;                  // named barrier per row

    __shared__ __align__(16) float hbuf[2][2][DH];   // [buf][rsel][j]

    // W_hh row j: 64 packed f32x2 pairs (128 registers).
    unsigned long long wp[64];
#pragma unroll
    for (int q = 0; q < 32; q++) {
        float4 v = *(const float4*)(Whh + j * DH + q * 4);
        wp[2 * q]     = pack2(v.x, v.y);
        wp[2 * q + 1] = pack2(v.z, v.w);
    }

    hbuf[0][rsel][j] = 0.0f;                    // h0 = 0

    // Distance-2 x prefetch (streaming loads).
    float xc = __ldcs(&g_xproj[(0 * BATCH + row) * DH + j]);
    float xn = __ldcs(&g_xproj[(1 * BATCH + row) * DH + j]);

    asm volatile("bar.sync %0, 128;" :: "r"(bar) : "memory");

    int   cur = 0;
    float hn  = 0.0f;
    for (int s = 0; s < SEQ; s++) {
        const int sp = (s + 2 < SEQ) ? (s + 2) : (SEQ - 1);
        float xf = __ldcs(&g_xproj[(sp * BATCH + row) * DH + j]);

        const float* h = hbuf[cur][rsel];
        unsigned long long acc[8] = {0ULL,0ULL,0ULL,0ULL,0ULL,0ULL,0ULL,0ULL};
#pragma unroll
        for (int q = 0; q < 16; q++) {          // 8 floats of h per iter
            ulonglong2 p0 = *(const ulonglong2*)(h + q * 8);
            ulonglong2 p1 = *(const ulonglong2*)(h + q * 8 + 4);
            const int base = (q & 1) * 4;       // 8 chains, each depth 8
            ffma2(acc[base + 0], wp[4 * q + 0], p0.x);
            ffma2(acc[base + 1], wp[4 * q + 1], p0.y);
            ffma2(acc[base + 2], wp[4 * q + 2], p1.x);
            ffma2(acc[base + 3], wp[4 * q + 3], p1.y);
        }
        // Packed reduction tree: 7 f32x2 adds (depth 3) + one scalar add.
        unsigned long long t0 = fadd2(acc[0], acc[1]);
        unsigned long long t1 = fadd2(acc[2], acc[3]);
        unsigned long long t2 = fadd2(acc[4], acc[5]);
        unsigned long long t3 = fadd2(acc[6], acc[7]);
        unsigned long long u  = fadd2(fadd2(t0, t1), fadd2(t2, t3));
        float2 f = unpack2(u);

        hn = fast_tanh(xc + (f.x + f.y));

        hbuf[cur ^ 1][rsel][j] = hn;            // publish into other buffer
        xc = xn; xn = xf;
        cur ^= 1;
        asm volatile("bar.sync %0, 128;" :: "r"(bar) : "memory");
    }

    out[row * DH + j] = hn;
}

// ---------------------------------------------------------------------------
// Launch.
// ---------------------------------------------------------------------------
extern "C" void kernel_launch(void* const* d_in, const int* in_sizes, int n_in,
                              void* d_out, int out_size) {
    const float* input = nullptr;
    const float* Wih   = nullptr;
    const float* Whh   = nullptr;
    const float* bA    = nullptr;
    const float* bB    = nullptr;

    for (int i = 0; i < n_in; i++) {
        const int sz = in_sizes[i];
        const float* p = (const float*)d_in[i];
        if      (sz == SEQ * BATCH * DIN) input = p;
        else if (sz == DH * DIN)          Wih   = p;
        else if (sz == DH * DH)           Whh   = p;
        else if (sz == DH)                { if (!bA) bA = p; else bB = p; }
    }

    xproj_kernel<<<2048, 128>>>(input, Wih, bA, bB);
    rnn_scan_kernel<<<BATCH / 2, 256>>>(Whh, (float*)d_out);
}